// round 1
// baseline (speedup 1.0000x reference)
#include <cuda_runtime.h>
#include <math.h>

#define BB 2048
#define SS 200
#define DD 192
#define H1 64
#define H2 32
#define NT 256

// smem floats: q(192) + weff(12288) + bias1(64) + w2(2048) + w3(32) + b2(32) + wgt(256) + red(256)
#define SMEM_FLOATS (192 + 12288 + 64 + 2048 + 32 + 32 + 256 + 256)

__global__ __launch_bounds__(NT, 2)
void rich_attn_kernel(const float* __restrict__ query,
                      const float* __restrict__ keys,
                      const int*   __restrict__ kmask,
                      const float* __restrict__ W1,
                      const float* __restrict__ b1,
                      const float* __restrict__ a1p,
                      const float* __restrict__ W2,
                      const float* __restrict__ b2,
                      const float* __restrict__ a2p,
                      const float* __restrict__ W3,
                      const float* __restrict__ b3p,
                      float* __restrict__ out)
{
    extern __shared__ float sm[];
    float* qs    = sm;             // 192
    float* weff  = qs + 192;       // 12288, layout [i][h]
    float* bias1 = weff + 12288;   // 64
    float* w2s   = bias1 + 64;     // 2048, layout [h][k]
    float* w3s   = w2s + 2048;     // 32
    float* b2s   = w3s + 32;       // 32
    float* wgt   = b2s + 32;       // 256
    float* red   = wgt + 256;      // 256

    const int tid = threadIdx.x;
    const int b   = blockIdx.x;

    const float a1 = a1p[0];
    const float a2 = a2p[0];
    const float b3 = b3p[0];

    // ---- load q ----
    if (tid < DD) qs[tid] = query[(size_t)b * DD + tid];
    // ---- small weights ----
    for (int idx = tid; idx < H1 * H2; idx += NT) w2s[idx] = W2[idx];
    if (tid < H2) { w3s[tid] = W3[tid]; b2s[tid] = b2[tid]; }
    __syncthreads();

    // ---- build W_eff: [192][64] ----
    // W_eff[i,h] = W1[i,h] + W1[576+i,h] + q_i * W1[384+i,h]
    for (int idx = tid; idx < DD * H1; idx += NT) {
        int i = idx >> 6;
        weff[idx] = W1[idx] + W1[(576 + i) * H1 + (idx & 63)]
                  + qs[i] * W1[(384 + i) * H1 + (idx & 63)];
    }
    // ---- bias1[h] = b1[h] + sum_i q_i * (W1[192+i,h] - W1[576+i,h]) ----
    if (tid < H1) {
        float acc = b1[tid];
        for (int i = 0; i < DD; i++)
            acc += qs[i] * (W1[(192 + i) * H1 + tid] - W1[(576 + i) * H1 + tid]);
        bias1[tid] = acc;
    }
    __syncthreads();

    // ---- per-s MLP pipeline ----
    const int s = tid;
    float score = -INFINITY;
    bool valid = false;

    if (s < SS) {
        valid = (kmask[(size_t)b * SS + s] != 0);

        const float* krow = keys + ((size_t)b * SS + s) * DD;
        float acc[H1];
        #pragma unroll
        for (int h = 0; h < H1; h++) acc[h] = bias1[h];

        for (int i = 0; i < DD; i += 4) {
            float4 kv = *reinterpret_cast<const float4*>(krow + i);
            const float* kvp = reinterpret_cast<const float*>(&kv);
            #pragma unroll
            for (int ii = 0; ii < 4; ii++) {
                float kvv = kvp[ii];
                const float4* wrow = reinterpret_cast<const float4*>(weff + (i + ii) * H1);
                #pragma unroll
                for (int h4 = 0; h4 < H1 / 4; h4++) {
                    float4 wv = wrow[h4];
                    acc[h4 * 4 + 0] = fmaf(kvv, wv.x, acc[h4 * 4 + 0]);
                    acc[h4 * 4 + 1] = fmaf(kvv, wv.y, acc[h4 * 4 + 1]);
                    acc[h4 * 4 + 2] = fmaf(kvv, wv.z, acc[h4 * 4 + 2]);
                    acc[h4 * 4 + 3] = fmaf(kvv, wv.w, acc[h4 * 4 + 3]);
                }
            }
        }
        // prelu layer 1
        #pragma unroll
        for (int h = 0; h < H1; h++) acc[h] = (acc[h] >= 0.f) ? acc[h] : a1 * acc[h];

        // layer 2: 64 -> 32
        float acc2[H2];
        #pragma unroll
        for (int k = 0; k < H2; k++) acc2[k] = b2s[k];
        #pragma unroll 4
        for (int h = 0; h < H1; h++) {
            float hv = acc[h];
            const float4* wrow = reinterpret_cast<const float4*>(w2s + h * H2);
            #pragma unroll
            for (int k4 = 0; k4 < H2 / 4; k4++) {
                float4 wv = wrow[k4];
                acc2[k4 * 4 + 0] = fmaf(hv, wv.x, acc2[k4 * 4 + 0]);
                acc2[k4 * 4 + 1] = fmaf(hv, wv.y, acc2[k4 * 4 + 1]);
                acc2[k4 * 4 + 2] = fmaf(hv, wv.z, acc2[k4 * 4 + 2]);
                acc2[k4 * 4 + 3] = fmaf(hv, wv.w, acc2[k4 * 4 + 3]);
            }
        }
        #pragma unroll
        for (int k = 0; k < H2; k++) acc2[k] = (acc2[k] >= 0.f) ? acc2[k] : a2 * acc2[k];

        // layer 3: 32 -> 1
        float sc = b3;
        #pragma unroll
        for (int k = 0; k < H2; k++) sc = fmaf(acc2[k], w3s[k], sc);
        score = sc;
    }

    // ---- masked softmax over s (block-wide) ----
    float mval = (valid) ? score : -INFINITY;
    red[tid] = mval;
    __syncthreads();
    for (int off = NT / 2; off > 0; off >>= 1) {
        if (tid < off) red[tid] = fmaxf(red[tid], red[tid + off]);
        __syncthreads();
    }
    float m = red[0];
    __syncthreads();

    float e = (valid && m > -INFINITY) ? expf(score - m) : 0.f;
    red[tid] = e;
    __syncthreads();
    for (int off = NT / 2; off > 0; off >>= 1) {
        if (tid < off) red[tid] += red[tid + off];
        __syncthreads();
    }
    float ssum = red[0];
    __syncthreads();

    float wv = (ssum > 0.f) ? (e / ssum) : 0.f;
    wgt[tid] = wv;
    if (s < SS) out[(size_t)BB * DD + (size_t)b * SS + s] = wv;
    __syncthreads();

    // ---- weighted sum over keys: out[b, d] = sum_s w[s] * keys[b, s, d] ----
    if (tid < DD) {
        const float* kb = keys + (size_t)b * SS * DD + tid;
        float acc = 0.f;
        #pragma unroll 4
        for (int si = 0; si < SS; si++)
            acc = fmaf(wgt[si], kb[(size_t)si * DD], acc);
        out[(size_t)b * DD + tid] = acc;
    }
}

extern "C" void kernel_launch(void* const* d_in, const int* in_sizes, int n_in,
                              void* d_out, int out_size)
{
    const float* query = (const float*)d_in[0];
    const float* keys  = (const float*)d_in[1];
    const int*   mask  = (const int*)  d_in[2];
    const float* W1    = (const float*)d_in[3];
    const float* b1    = (const float*)d_in[4];
    const float* a1    = (const float*)d_in[5];
    const float* W2    = (const float*)d_in[6];
    const float* b2    = (const float*)d_in[7];
    const float* a2    = (const float*)d_in[8];
    const float* W3    = (const float*)d_in[9];
    const float* b3    = (const float*)d_in[10];
    float* out = (float*)d_out;

    static bool attr_set = false;
    if (!attr_set) {
        cudaFuncSetAttribute(rich_attn_kernel,
                             cudaFuncAttributeMaxDynamicSharedMemorySize,
                             SMEM_FLOATS * sizeof(float));
        attr_set = true;
    }

    rich_attn_kernel<<<BB, NT, SMEM_FLOATS * sizeof(float)>>>(
        query, keys, mask, W1, b1, a1, W2, b2, a2, W3, b3, out);
}